// round 1
// baseline (speedup 1.0000x reference)
#include <cuda_runtime.h>
#include <cuda_bf16.h>
#include <float.h>

// Problem dims
#define N_ROWS 16384     // 32*512
#define K_EMB  8192
#define D_DIM  256
#define NQ_ELEMS (N_ROWS * D_DIM)   // 4194304

// Main-kernel tiling
#define BM 128
#define BN 128
#define BK 32
#define XS_STRIDE 260    // 256 + 4: multiple of 4 (float4-aligned rows), 260%32=4 -> conflict-free for 2-row frag reads
#define ES_STRIDE 33     // odd -> 16 distinct banks for the 16 tx fragment rows

// Scratch (no allocations allowed -> device globals)
__device__ float g_enorm[K_EMB];
__device__ int   g_indices[N_ROWS];
__device__ float g_partial[2048];

// ---------------------------------------------------------------------------
// Kernel 1: ||e_k||^2 per codebook row. One warp per row.
// ---------------------------------------------------------------------------
__global__ void vq_enorm_kernel(const float* __restrict__ emb) {
    int gw   = (blockIdx.x * blockDim.x + threadIdx.x) >> 5;  // global warp = row
    int lane = threadIdx.x & 31;
    if (gw >= K_EMB) return;
    const float4* e4 = reinterpret_cast<const float4*>(emb + (size_t)gw * D_DIM);
    float s = 0.f;
#pragma unroll
    for (int i = 0; i < 2; ++i) {
        float4 v = e4[lane + 32 * i];
        s += v.x * v.x + v.y * v.y + v.z * v.z + v.w * v.w;
    }
#pragma unroll
    for (int off = 16; off >= 1; off >>= 1)
        s += __shfl_xor_sync(0xffffffffu, s, off);
    if (lane == 0) g_enorm[gw] = s;
}

// ---------------------------------------------------------------------------
// Kernel 2: fused distance + argmin.
// Grid = N_ROWS/BM = 128 CTAs, 256 threads (16x16). Each CTA: 128 rows x all K.
// X tile resident in SMEM for the whole CTA; E streamed in [128 x 32] chunks.
// Thread (tx,ty) owns rows {ty+16i}, cols {tx+16j}, i,j in 0..7.
// ---------------------------------------------------------------------------
__global__ void __launch_bounds__(256, 1)
vq_argmin_kernel(const float* __restrict__ X, const float* __restrict__ E) {
    extern __shared__ float smem[];
    float* Xs  = smem;                       // [BM][XS_STRIDE]
    float* Es  = Xs + BM * XS_STRIDE;        // [BN][ES_STRIDE]
    float* Ens = Es + BN * ES_STRIDE;        // [BN]

    const int tid = threadIdx.x;
    const int tx  = tid & 15;
    const int ty  = tid >> 4;
    const int rowbase = blockIdx.x * BM;

    // Load X tile [BM][D] -> padded SMEM, float4 vectorized, coalesced.
#pragma unroll
    for (int t = 0; t < 32; ++t) {
        int idx = tid + t * 256;             // 0..8191 float4s
        int r  = idx >> 6;                   // 64 float4 per row
        int c4 = idx & 63;
        float4 v = *reinterpret_cast<const float4*>(X + (size_t)(rowbase + r) * D_DIM + c4 * 4);
        *reinterpret_cast<float4*>(&Xs[r * XS_STRIDE + c4 * 4]) = v;
    }
    __syncthreads();

    float minval[8];
    int   minidx[8];
#pragma unroll
    for (int i = 0; i < 8; ++i) { minval[i] = FLT_MAX; minidx[i] = 0; }

    for (int kb = 0; kb < K_EMB / BN; ++kb) {
        // Protect Es/Ens reuse from previous iteration's readers.
        __syncthreads();
        if (tid < BN) Ens[tid] = g_enorm[kb * BN + tid];

        float acc[8][8];
#pragma unroll
        for (int i = 0; i < 8; ++i)
#pragma unroll
            for (int j = 0; j < 8; ++j) acc[i][j] = 0.f;

        for (int dstep = 0; dstep < D_DIM / BK; ++dstep) {
            // Load E chunk [BN][BK] (1024 float4s; 4 per thread). Scalar SMEM
            // stores (odd stride). First pass also covered by the sync above.
#pragma unroll
            for (int t = 0; t < 4; ++t) {
                int idx = tid + t * 256;          // 0..1023
                int r  = idx >> 3;                // 8 float4 per row
                int c4 = idx & 7;
                float4 v = *reinterpret_cast<const float4*>(
                    E + (size_t)(kb * BN + r) * D_DIM + dstep * BK + c4 * 4);
                float* dst = &Es[r * ES_STRIDE + c4 * 4];
                dst[0] = v.x; dst[1] = v.y; dst[2] = v.z; dst[3] = v.w;
            }
            __syncthreads();

            const float* xbase = &Xs[ty * XS_STRIDE + dstep * BK];
            const float* ebase = &Es[tx * ES_STRIDE];
#pragma unroll
            for (int d = 0; d < BK; ++d) {
                float xf[8], ef[8];
#pragma unroll
                for (int i = 0; i < 8; ++i) xf[i] = xbase[i * 16 * XS_STRIDE + d];
#pragma unroll
                for (int j = 0; j < 8; ++j) ef[j] = ebase[j * 16 * ES_STRIDE + d];
#pragma unroll
                for (int i = 0; i < 8; ++i)
#pragma unroll
                    for (int j = 0; j < 8; ++j) acc[i][j] = fmaf(xf[i], ef[j], acc[i][j]);
            }
            __syncthreads();
        }

        // dist = ||e||^2 - 2 x.e  (per-row ||x||^2 is argmin-invariant).
        // Iteration order is strictly increasing gk, so strict < keeps the
        // first-occurrence (smallest index) semantics of jnp.argmin.
#pragma unroll
        for (int j = 0; j < 8; ++j) {
            int col = tx + 16 * j;
            float en = Ens[col];
            int gk = kb * BN + col;
#pragma unroll
            for (int i = 0; i < 8; ++i) {
                float dist = en - 2.0f * acc[i][j];
                if (dist < minval[i]) { minval[i] = dist; minidx[i] = gk; }
            }
        }
    }

    // Cross-thread argmin over tx (the 16 lanes of a half-warp share rows).
#pragma unroll
    for (int i = 0; i < 8; ++i) {
        float v = minval[i];
        int   ix = minidx[i];
#pragma unroll
        for (int off = 8; off >= 1; off >>= 1) {
            float v2 = __shfl_xor_sync(0xffffffffu, v, off);
            int   i2 = __shfl_xor_sync(0xffffffffu, ix, off);
            if (v2 < v || (v2 == v && i2 < ix)) { v = v2; ix = i2; }
        }
        if (tx == 0) g_indices[rowbase + ty + 16 * i] = ix;
    }
}

// ---------------------------------------------------------------------------
// Kernel 3: gather quantized rows + per-block partial sums of (q-x)^2.
// One warp per row. 2048 blocks x 256 threads.
// ---------------------------------------------------------------------------
__global__ void vq_gather_kernel(const float* __restrict__ X,
                                 const float* __restrict__ E,
                                 float* __restrict__ out_q,     // may be null
                                 float* __restrict__ out_idx_f, // may be null
                                 int*   __restrict__ out_idx_i) // may be null
{
    __shared__ float wsum[8];
    int warp = threadIdx.x >> 5;
    int lane = threadIdx.x & 31;
    int row  = blockIdx.x * 8 + warp;

    int idx = g_indices[row];
    const float4* x4 = reinterpret_cast<const float4*>(X + (size_t)row * D_DIM);
    const float4* e4 = reinterpret_cast<const float4*>(E + (size_t)idx * D_DIM);

    float s = 0.f;
#pragma unroll
    for (int t = 0; t < 2; ++t) {
        int c = lane + 32 * t;
        float4 xv = x4[c];
        float4 ev = e4[c];
        if (out_q) reinterpret_cast<float4*>(out_q + (size_t)row * D_DIM)[c] = ev;
        float dx = ev.x - xv.x, dy = ev.y - xv.y, dz = ev.z - xv.z, dw = ev.w - xv.w;
        s += dx * dx + dy * dy + dz * dz + dw * dw;
    }
#pragma unroll
    for (int off = 16; off >= 1; off >>= 1)
        s += __shfl_xor_sync(0xffffffffu, s, off);
    if (lane == 0) {
        wsum[warp] = s;
        if (out_idx_f) out_idx_f[row] = (float)idx;
        if (out_idx_i) out_idx_i[row] = idx;
    }
    __syncthreads();
    if (threadIdx.x == 0) {
        float t = 0.f;
#pragma unroll
        for (int w = 0; w < 8; ++w) t += wsum[w];
        g_partial[blockIdx.x] = t;
    }
}

// ---------------------------------------------------------------------------
// Kernel 4: deterministic loss reduction. loss = m + 0.25*m, m = sum/NQ.
// ---------------------------------------------------------------------------
__global__ void vq_loss_kernel(float* __restrict__ out_loss) {
    __shared__ float red[256];
    float s = 0.f;
#pragma unroll
    for (int t = 0; t < 8; ++t) s += g_partial[threadIdx.x + t * 256];
    red[threadIdx.x] = s;
    __syncthreads();
    for (int off = 128; off >= 1; off >>= 1) {
        if (threadIdx.x < off) red[threadIdx.x] += red[threadIdx.x + off];
        __syncthreads();
    }
    if (threadIdx.x == 0) {
        float m = red[0] / (float)NQ_ELEMS;
        *out_loss = m + 0.25f * m;
    }
}

// ---------------------------------------------------------------------------
extern "C" void kernel_launch(void* const* d_in, const int* in_sizes, int n_in,
                              void* d_out, int out_size) {
    const float* X = (const float*)d_in[0];   // inputs  [32,512,256]
    const float* E = (const float*)d_in[1];   // embeddings [8192,256]
    float* out = (float*)d_out;

    // Output layout decoded from out_size (reference returns quantized_st,
    // loss, encoding_indices in that order).
    float* out_q     = nullptr;
    float* out_loss  = nullptr;
    float* out_idx_f = nullptr;
    int*   out_idx_i = nullptr;

    if (out_size == NQ_ELEMS) {
        out_q = out;
    } else if (out_size == NQ_ELEMS + 1) {
        out_q = out; out_loss = out + NQ_ELEMS;
    } else if (out_size == NQ_ELEMS + 1 + N_ROWS) {
        out_q = out; out_loss = out + NQ_ELEMS; out_idx_f = out + NQ_ELEMS + 1;
    } else if (out_size == NQ_ELEMS + N_ROWS) {
        out_q = out; out_idx_f = out + NQ_ELEMS;
    } else if (out_size == N_ROWS) {
        out_idx_i = (int*)d_out;
    } else {
        // Fallback: assume quantized-first.
        out_q = out;
    }

    // 1) codebook norms
    vq_enorm_kernel<<<K_EMB / 8, 256>>>(E);

    // 2) fused distance + argmin
    const int smem_bytes = (BM * XS_STRIDE + BN * ES_STRIDE + BN) * (int)sizeof(float);
    cudaFuncSetAttribute(vq_argmin_kernel, cudaFuncAttributeMaxDynamicSharedMemorySize, smem_bytes);
    vq_argmin_kernel<<<N_ROWS / BM, 256, smem_bytes>>>(X, E);

    // 3) gather + partial loss sums
    vq_gather_kernel<<<N_ROWS / 8, 256>>>(X, E, out_q, out_idx_f, out_idx_i);

    // 4) loss scalar
    if (out_loss) vq_loss_kernel<<<1, 256>>>(out_loss);
}

// round 3
// speedup vs baseline: 3.7176x; 3.7176x over previous
#include <cuda_runtime.h>
#include <cuda_bf16.h>
#include <float.h>
#include <stdint.h>

// ---------------------------------------------------------------------------
// Problem dims
// ---------------------------------------------------------------------------
#define N_ROWS 16384     // 32*512
#define K_EMB  8192
#define D_DIM  256
#define NQ_ELEMS (N_ROWS * D_DIM)   // 4194304

// Coarse-kernel tiling
#define BM 128           // rows per CTA
#define BN 128           // codes per col-block
#define NBLK (K_EMB / BN)    // 64
#define XS 264           // padded bf16 row stride (528B -> +4 banks/row)
#define MARGIN 3.0f
#define CAND_CAP 64

// ---------------------------------------------------------------------------
// Scratch (device globals; no allocations allowed)
// ---------------------------------------------------------------------------
__device__ float          g_enorm[K_EMB];
__device__ int            g_indices[N_ROWS];
__device__ float          g_partial[2048];
__device__ __nv_bfloat16  g_Xb[NQ_ELEMS];
__device__ __nv_bfloat16  g_Eb[K_EMB * D_DIM];
__device__ int            g_candcnt[N_ROWS];
__device__ int            g_cand[N_ROWS * CAND_CAP];

// ---------------------------------------------------------------------------
// Helpers
// ---------------------------------------------------------------------------
__device__ __forceinline__ unsigned enc_f(float f) {
    unsigned u = __float_as_uint(f);
    return (u & 0x80000000u) ? ~u : (u | 0x80000000u);
}
__device__ __forceinline__ float dec_f(unsigned k) {
    return (k & 0x80000000u) ? __uint_as_float(k & 0x7FFFFFFFu)
                             : __uint_as_float(~k);
}

__device__ __forceinline__ void cp_async16(void* smem_dst, const void* gsrc) {
    unsigned saddr = (unsigned)__cvta_generic_to_shared(smem_dst);
    asm volatile("cp.async.cg.shared.global [%0], [%1], 16;"
                 :: "r"(saddr), "l"(gsrc) : "memory");
}
__device__ __forceinline__ void cp_commit() {
    asm volatile("cp.async.commit_group;" ::: "memory");
}
__device__ __forceinline__ void cp_wait1() {
    asm volatile("cp.async.wait_group 1;" ::: "memory");
}
__device__ __forceinline__ void cp_wait0() {
    asm volatile("cp.async.wait_group 0;" ::: "memory");
}

__device__ __forceinline__ void mma_bf16(float* d, const uint32_t* a,
                                         uint32_t b0, uint32_t b1) {
    asm volatile(
        "mma.sync.aligned.m16n8k16.row.col.f32.bf16.bf16.f32 "
        "{%0,%1,%2,%3}, {%4,%5,%6,%7}, {%8,%9}, {%0,%1,%2,%3};"
        : "+f"(d[0]), "+f"(d[1]), "+f"(d[2]), "+f"(d[3])
        : "r"(a[0]), "r"(a[1]), "r"(a[2]), "r"(a[3]), "r"(b0), "r"(b1));
}

// ---------------------------------------------------------------------------
// Kernel A: fp32 -> bf16 (rn). n4 = n/4.
// ---------------------------------------------------------------------------
__global__ void vq_tobf16_kernel(const float* __restrict__ src,
                                 __nv_bfloat16* __restrict__ dst, int n4) {
    int i = blockIdx.x * blockDim.x + threadIdx.x;
    if (i >= n4) return;
    float4 v = reinterpret_cast<const float4*>(src)[i];
    __nv_bfloat162* d2 = reinterpret_cast<__nv_bfloat162*>(dst);
    d2[2 * i + 0] = __floats2bfloat162_rn(v.x, v.y);
    d2[2 * i + 1] = __floats2bfloat162_rn(v.z, v.w);
}

// ---------------------------------------------------------------------------
// Kernel B: ||e_k||^2 (fp32) + zero candidate counters.
// ---------------------------------------------------------------------------
__global__ void vq_enorm_kernel(const float* __restrict__ emb) {
    int gt = blockIdx.x * blockDim.x + threadIdx.x;
    if (gt < N_ROWS) g_candcnt[gt] = 0;
    int gw   = gt >> 5;
    int lane = threadIdx.x & 31;
    if (gw >= K_EMB) return;
    const float4* e4 = reinterpret_cast<const float4*>(emb + (size_t)gw * D_DIM);
    float s = 0.f;
#pragma unroll
    for (int i = 0; i < 2; ++i) {
        float4 v = e4[lane + 32 * i];
        s += v.x * v.x + v.y * v.y + v.z * v.z + v.w * v.w;
    }
#pragma unroll
    for (int off = 16; off >= 1; off >>= 1)
        s += __shfl_xor_sync(0xffffffffu, s, off);
    if (lane == 0) g_enorm[gw] = s;
}

// ---------------------------------------------------------------------------
// Kernel C: coarse bf16 GEMM (mma.sync) + running row-min + candidate collect.
// Grid = 128 CTAs (128 rows each), 256 threads (8 warps, 4x2).
// Warp tile 32x64; per-thread acc 2(mt) x 8(nt) x 4.
// ---------------------------------------------------------------------------
__global__ void __launch_bounds__(256, 1)
vq_coarse_kernel() {
    extern __shared__ __align__(16) char smem[];
    __nv_bfloat16* Xs  = reinterpret_cast<__nv_bfloat16*>(smem);
    __nv_bfloat16* Es0 = Xs + BM * XS;
    __nv_bfloat16* Es1 = Es0 + BN * XS;
    float*    ensS    = reinterpret_cast<float*>(Es1 + BN * XS);  // [2][128]
    unsigned* rowminS = reinterpret_cast<unsigned*>(ensS + 2 * BN);

    const int tid  = threadIdx.x;
    const int warp = tid >> 5;
    const int lane = tid & 31;
    const int wm   = warp >> 1;      // 0..3
    const int wn   = warp & 1;       // 0..1
    const int rowbase = blockIdx.x * BM;
    const int lrow4 = lane >> 2;     // 0..7
    const int lcol2 = (lane & 3) * 2;

    // Resident X tile [128][256] bf16 (padded rows)
#pragma unroll
    for (int t = 0; t < 16; ++t) {
        int idx = tid + t * 256;
        int r = idx >> 5, c8 = idx & 31;
        float4 v = *reinterpret_cast<const float4*>(g_Xb + (size_t)(rowbase + r) * D_DIM + c8 * 8);
        *reinterpret_cast<float4*>(Xs + r * XS + c8 * 8) = v;
    }
    if (tid < BM) rowminS[tid] = 0xFFFFFFFFu;

    // Async-load one E col-block (+ its enorms) into buffer `buf`
    auto load_blk = [&](int blk, int buf) {
        __nv_bfloat16* dst = buf ? Es1 : Es0;
        const __nv_bfloat16* src = g_Eb + (size_t)blk * BN * D_DIM;
#pragma unroll
        for (int t = 0; t < 16; ++t) {
            int idx = tid + t * 256;
            int r = idx >> 5, c8 = idx & 31;
            cp_async16(dst + r * XS + c8 * 8, src + r * D_DIM + c8 * 8);
        }
        if (tid < 32)
            cp_async16(&ensS[buf * BN + tid * 4], &g_enorm[blk * BN + tid * 4]);
    };

    load_blk(0, 0);
    cp_commit();

    const __nv_bfloat16* xa = Xs + (wm * 32 + lrow4) * XS + lcol2;

    for (int blk = 0; blk < NBLK; ++blk) {
        const int buf = blk & 1;
        if (blk + 1 < NBLK) { load_blk(blk + 1, buf ^ 1); cp_commit(); cp_wait1(); }
        else cp_wait0();
        __syncthreads();

        float acc[2][8][4];
#pragma unroll
        for (int mt = 0; mt < 2; ++mt)
#pragma unroll
            for (int nt = 0; nt < 8; ++nt)
#pragma unroll
                for (int i = 0; i < 4; ++i) acc[mt][nt][i] = 0.f;

        const __nv_bfloat16* Eb = buf ? Es1 : Es0;
        const __nv_bfloat16* eb = Eb + (wn * 64 + lrow4) * XS + lcol2;

#pragma unroll
        for (int ks = 0; ks < 16; ++ks) {
            const int k0 = ks * 16;
            uint32_t A[2][4];
#pragma unroll
            for (int mt = 0; mt < 2; ++mt) {
                const __nv_bfloat16* p = xa + mt * 16 * XS + k0;
                A[mt][0] = *reinterpret_cast<const uint32_t*>(p);
                A[mt][1] = *reinterpret_cast<const uint32_t*>(p + 8 * XS);
                A[mt][2] = *reinterpret_cast<const uint32_t*>(p + 8);
                A[mt][3] = *reinterpret_cast<const uint32_t*>(p + 8 * XS + 8);
            }
#pragma unroll
            for (int nt = 0; nt < 8; ++nt) {
                const __nv_bfloat16* p = eb + nt * 8 * XS + k0;
                uint32_t b0 = *reinterpret_cast<const uint32_t*>(p);
                uint32_t b1 = *reinterpret_cast<const uint32_t*>(p + 8);
                mma_bf16(acc[0][nt], A[0], b0, b1);
                mma_bf16(acc[1][nt], A[1], b0, b1);
            }
        }

        // dist = ||e||^2 - 2 x.e  (||x||^2 argmin-invariant)
        float e2[8][2];
#pragma unroll
        for (int nt = 0; nt < 8; ++nt) {
            int c = wn * 64 + nt * 8 + lcol2;
            e2[nt][0] = ensS[buf * BN + c];
            e2[nt][1] = ensS[buf * BN + c + 1];
        }
        float smin[4] = {FLT_MAX, FLT_MAX, FLT_MAX, FLT_MAX};
#pragma unroll
        for (int mt = 0; mt < 2; ++mt)
#pragma unroll
            for (int nt = 0; nt < 8; ++nt)
#pragma unroll
                for (int i = 0; i < 4; ++i) {
                    float d = fmaf(-2.0f, acc[mt][nt][i], e2[nt][i & 1]);
                    acc[mt][nt][i] = d;
                    int s = mt * 2 + (i >> 1);
                    smin[s] = fminf(smin[s], d);
                }
        // reduce the 4 lanes that share each row (lane&3 group)
#pragma unroll
        for (int s = 0; s < 4; ++s) {
            smin[s] = fminf(smin[s], __shfl_xor_sync(0xffffffffu, smin[s], 1));
            smin[s] = fminf(smin[s], __shfl_xor_sync(0xffffffffu, smin[s], 2));
        }
        if ((lane & 3) == 0) {
#pragma unroll
            for (int s = 0; s < 4; ++s) {
                int lr = wm * 32 + (s >> 1) * 16 + lrow4 + 8 * (s & 1);
                atomicMin(&rowminS[lr], enc_f(smin[s]));
            }
        }
        __syncthreads();

        float thr[4];
#pragma unroll
        for (int s = 0; s < 4; ++s) {
            int lr = wm * 32 + (s >> 1) * 16 + lrow4 + 8 * (s & 1);
            thr[s] = dec_f(rowminS[lr]) + MARGIN;
        }
#pragma unroll
        for (int mt = 0; mt < 2; ++mt)
#pragma unroll
            for (int nt = 0; nt < 8; ++nt)
#pragma unroll
                for (int i = 0; i < 4; ++i) {
                    int s = mt * 2 + (i >> 1);
                    if (acc[mt][nt][i] < thr[s]) {
                        int lr = wm * 32 + mt * 16 + lrow4 + 8 * (i >> 1);
                        int grow = rowbase + lr;
                        int gcol = blk * BN + wn * 64 + nt * 8 + lcol2 + (i & 1);
                        int pos = atomicAdd(&g_candcnt[grow], 1);
                        if (pos < CAND_CAP) g_cand[grow * CAND_CAP + pos] = gcol;
                    }
                }
        __syncthreads();
    }
}

// ---------------------------------------------------------------------------
// Kernel D: exact fp32 rescue over candidates. One warp per row.
// ---------------------------------------------------------------------------
__global__ void vq_rescue_kernel(const float* __restrict__ X,
                                 const float* __restrict__ E) {
    int warp = threadIdx.x >> 5;
    int lane = threadIdx.x & 31;
    int row  = blockIdx.x * 8 + warp;

    const float4* x4 = reinterpret_cast<const float4*>(X + (size_t)row * D_DIM);
    float4 xa = x4[lane];
    float4 xb = x4[lane + 32];

    int cnt = g_candcnt[row];
    float best = FLT_MAX;
    int   bidx = 0x7fffffff;

    auto eval = [&](int idx) {
        const float4* e4 = reinterpret_cast<const float4*>(E + (size_t)idx * D_DIM);
        float4 ea = e4[lane];
        float4 eb = e4[lane + 32];
        float p = xa.x * ea.x + xa.y * ea.y + xa.z * ea.z + xa.w * ea.w
                + xb.x * eb.x + xb.y * eb.y + xb.z * eb.z + xb.w * eb.w;
#pragma unroll
        for (int off = 16; off >= 1; off >>= 1)
            p += __shfl_xor_sync(0xffffffffu, p, off);
        float dist = g_enorm[idx] - 2.0f * p;
        if (dist < best || (dist == best && idx < bidx)) { best = dist; bidx = idx; }
    };

    if (cnt > 0 && cnt <= CAND_CAP) {
        for (int c = 0; c < cnt; ++c) eval(g_cand[row * CAND_CAP + c]);
    } else {
        for (int k = 0; k < K_EMB; ++k) eval(k);   // overflow fallback (rare)
    }
    if (lane == 0) g_indices[row] = bidx;
}

// ---------------------------------------------------------------------------
// Kernel E: gather quantized rows + partial loss sums.
// ---------------------------------------------------------------------------
__global__ void vq_gather_kernel(const float* __restrict__ X,
                                 const float* __restrict__ E,
                                 float* __restrict__ out_q,
                                 float* __restrict__ out_idx_f,
                                 int*   __restrict__ out_idx_i) {
    __shared__ float wsum[8];
    int warp = threadIdx.x >> 5;
    int lane = threadIdx.x & 31;
    int row  = blockIdx.x * 8 + warp;

    int idx = g_indices[row];
    const float4* x4 = reinterpret_cast<const float4*>(X + (size_t)row * D_DIM);
    const float4* e4 = reinterpret_cast<const float4*>(E + (size_t)idx * D_DIM);

    float s = 0.f;
#pragma unroll
    for (int t = 0; t < 2; ++t) {
        int c = lane + 32 * t;
        float4 xv = x4[c];
        float4 ev = e4[c];
        if (out_q) reinterpret_cast<float4*>(out_q + (size_t)row * D_DIM)[c] = ev;
        float dx = ev.x - xv.x, dy = ev.y - xv.y, dz = ev.z - xv.z, dw = ev.w - xv.w;
        s += dx * dx + dy * dy + dz * dz + dw * dw;
    }
#pragma unroll
    for (int off = 16; off >= 1; off >>= 1)
        s += __shfl_xor_sync(0xffffffffu, s, off);
    if (lane == 0) {
        wsum[warp] = s;
        if (out_idx_f) out_idx_f[row] = (float)idx;
        if (out_idx_i) out_idx_i[row] = idx;
    }
    __syncthreads();
    if (threadIdx.x == 0) {
        float t = 0.f;
#pragma unroll
        for (int w = 0; w < 8; ++w) t += wsum[w];
        g_partial[blockIdx.x] = t;
    }
}

// ---------------------------------------------------------------------------
// Kernel F: loss = m + 0.25*m, m = sum/NQ.
// ---------------------------------------------------------------------------
__global__ void vq_loss_kernel(float* __restrict__ out_loss) {
    __shared__ float red[256];
    float s = 0.f;
#pragma unroll
    for (int t = 0; t < 8; ++t) s += g_partial[threadIdx.x + t * 256];
    red[threadIdx.x] = s;
    __syncthreads();
    for (int off = 128; off >= 1; off >>= 1) {
        if (threadIdx.x < off) red[threadIdx.x] += red[threadIdx.x + off];
        __syncthreads();
    }
    if (threadIdx.x == 0) {
        float m = red[0] / (float)NQ_ELEMS;
        *out_loss = m + 0.25f * m;
    }
}

// ---------------------------------------------------------------------------
extern "C" void kernel_launch(void* const* d_in, const int* in_sizes, int n_in,
                              void* d_out, int out_size) {
    const float* X = (const float*)d_in[0];
    const float* E = (const float*)d_in[1];
    float* out = (float*)d_out;

    float* out_q     = nullptr;
    float* out_loss  = nullptr;
    float* out_idx_f = nullptr;
    int*   out_idx_i = nullptr;

    if (out_size == NQ_ELEMS) {
        out_q = out;
    } else if (out_size == NQ_ELEMS + 1) {
        out_q = out; out_loss = out + NQ_ELEMS;
    } else if (out_size == NQ_ELEMS + 1 + N_ROWS) {
        out_q = out; out_loss = out + NQ_ELEMS; out_idx_f = out + NQ_ELEMS + 1;
    } else if (out_size == NQ_ELEMS + N_ROWS) {
        out_q = out; out_idx_f = out + NQ_ELEMS;
    } else if (out_size == N_ROWS) {
        out_idx_i = (int*)d_out;
    } else {
        out_q = out;
    }

    __nv_bfloat16 *dXb, *dEb;
    cudaGetSymbolAddress((void**)&dXb, g_Xb);
    cudaGetSymbolAddress((void**)&dEb, g_Eb);

    // A) bf16 copies
    vq_tobf16_kernel<<<NQ_ELEMS / 4 / 256, 256>>>(X, dXb, NQ_ELEMS / 4);
    vq_tobf16_kernel<<<K_EMB * D_DIM / 4 / 256, 256>>>(E, dEb, K_EMB * D_DIM / 4);

    // B) codebook norms + zero cand counters
    vq_enorm_kernel<<<K_EMB / 8, 256>>>(E);

    // C) coarse bf16 mma + candidate collection
    const int smem_bytes = (BM * XS + 2 * BN * XS) * 2 + 2 * BN * 4 + BM * 4;
    cudaFuncSetAttribute(vq_coarse_kernel,
                         cudaFuncAttributeMaxDynamicSharedMemorySize, smem_bytes);
    vq_coarse_kernel<<<N_ROWS / BM, 256, smem_bytes>>>();

    // D) exact fp32 rescue
    vq_rescue_kernel<<<N_ROWS / 8, 256>>>(X, E);

    // E) gather + partial loss sums
    vq_gather_kernel<<<N_ROWS / 8, 256>>>(X, E, out_q, out_idx_f, out_idx_i);

    // F) loss scalar
    if (out_loss) vq_loss_kernel<<<1, 256>>>(out_loss);
}

// round 4
// speedup vs baseline: 4.0779x; 1.0969x over previous
#include <cuda_runtime.h>
#include <cuda_bf16.h>
#include <float.h>
#include <stdint.h>

// ---------------------------------------------------------------------------
// Problem dims
// ---------------------------------------------------------------------------
#define N_ROWS 16384     // 32*512
#define K_EMB  8192
#define D_DIM  256
#define NQ_ELEMS (N_ROWS * D_DIM)   // 4194304

// Coarse-kernel tiling
#define BM 128           // rows per CTA
#define BN 128           // codes per col-block
#define NBLK (K_EMB / BN)    // 64
#define XS 264           // padded bf16 row stride: 528B -> 4-bank shift per row
#define MARGIN 3.0f
#define CAND_CAP 64
#define NTHR 512         // 16 warps: 4(m) x 4(n), warp tile 32x32

// ---------------------------------------------------------------------------
// Scratch (device globals; no allocations allowed)
// ---------------------------------------------------------------------------
__device__ float          g_enorm[K_EMB];
__device__ int            g_indices[N_ROWS];
__device__ float          g_partial[2048];
__device__ __nv_bfloat16  g_Xb[NQ_ELEMS];
__device__ __nv_bfloat16  g_Eb[K_EMB * D_DIM];
__device__ int            g_candcnt[N_ROWS];
__device__ int            g_cand[N_ROWS * CAND_CAP];

// ---------------------------------------------------------------------------
// Helpers
// ---------------------------------------------------------------------------
__device__ __forceinline__ unsigned enc_f(float f) {
    unsigned u = __float_as_uint(f);
    return (u & 0x80000000u) ? ~u : (u | 0x80000000u);
}
__device__ __forceinline__ float dec_f(unsigned k) {
    return (k & 0x80000000u) ? __uint_as_float(k & 0x7FFFFFFFu)
                             : __uint_as_float(~k);
}

__device__ __forceinline__ void cp_async16(void* smem_dst, const void* gsrc) {
    unsigned saddr = (unsigned)__cvta_generic_to_shared(smem_dst);
    asm volatile("cp.async.cg.shared.global [%0], [%1], 16;"
                 :: "r"(saddr), "l"(gsrc) : "memory");
}
__device__ __forceinline__ void cp_commit() {
    asm volatile("cp.async.commit_group;" ::: "memory");
}
__device__ __forceinline__ void cp_wait0() {
    asm volatile("cp.async.wait_group 0;" ::: "memory");
}

__device__ __forceinline__ void ldmat4(uint32_t& r0, uint32_t& r1,
                                       uint32_t& r2, uint32_t& r3, uint32_t addr) {
    asm volatile("ldmatrix.sync.aligned.m8n8.x4.shared.b16 {%0,%1,%2,%3}, [%4];"
                 : "=r"(r0), "=r"(r1), "=r"(r2), "=r"(r3) : "r"(addr));
}

__device__ __forceinline__ void mma_bf16(float* d, const uint32_t* a,
                                         uint32_t b0, uint32_t b1) {
    asm volatile(
        "mma.sync.aligned.m16n8k16.row.col.f32.bf16.bf16.f32 "
        "{%0,%1,%2,%3}, {%4,%5,%6,%7}, {%8,%9}, {%0,%1,%2,%3};"
        : "+f"(d[0]), "+f"(d[1]), "+f"(d[2]), "+f"(d[3])
        : "r"(a[0]), "r"(a[1]), "r"(a[2]), "r"(a[3]), "r"(b0), "r"(b1));
}

// ---------------------------------------------------------------------------
// Kernel A: fp32 -> bf16 (rn). n4 = n/4.
// ---------------------------------------------------------------------------
__global__ void vq_tobf16_kernel(const float* __restrict__ src,
                                 __nv_bfloat16* __restrict__ dst, int n4) {
    int i = blockIdx.x * blockDim.x + threadIdx.x;
    if (i >= n4) return;
    float4 v = reinterpret_cast<const float4*>(src)[i];
    __nv_bfloat162* d2 = reinterpret_cast<__nv_bfloat162*>(dst);
    d2[2 * i + 0] = __floats2bfloat162_rn(v.x, v.y);
    d2[2 * i + 1] = __floats2bfloat162_rn(v.z, v.w);
}

// ---------------------------------------------------------------------------
// Kernel B: ||e_k||^2 (fp32) + zero candidate counters.
// ---------------------------------------------------------------------------
__global__ void vq_enorm_kernel(const float* __restrict__ emb) {
    int gt = blockIdx.x * blockDim.x + threadIdx.x;
    if (gt < N_ROWS) g_candcnt[gt] = 0;
    int gw   = gt >> 5;
    int lane = threadIdx.x & 31;
    if (gw >= K_EMB) return;
    const float4* e4 = reinterpret_cast<const float4*>(emb + (size_t)gw * D_DIM);
    float s = 0.f;
#pragma unroll
    for (int i = 0; i < 2; ++i) {
        float4 v = e4[lane + 32 * i];
        s += v.x * v.x + v.y * v.y + v.z * v.z + v.w * v.w;
    }
#pragma unroll
    for (int off = 16; off >= 1; off >>= 1)
        s += __shfl_xor_sync(0xffffffffu, s, off);
    if (lane == 0) g_enorm[gw] = s;
}

// ---------------------------------------------------------------------------
// Kernel C: coarse bf16 GEMM (ldmatrix + mma.sync) + running row-min +
// candidate collection.
// Grid = 128 CTAs, 512 threads (16 warps: 4m x 4n). Warp tile 32x32.
// ---------------------------------------------------------------------------
__global__ void __launch_bounds__(NTHR, 1)
vq_coarse_kernel() {
    extern __shared__ __align__(16) char smem[];
    __nv_bfloat16* Xs  = reinterpret_cast<__nv_bfloat16*>(smem);
    __nv_bfloat16* Es0 = Xs + BM * XS;
    __nv_bfloat16* Es1 = Es0 + BN * XS;
    float*    ensS    = reinterpret_cast<float*>(Es1 + BN * XS);  // [2][128]
    unsigned* rowminS = reinterpret_cast<unsigned*>(ensS + 2 * BN);

    const int tid  = threadIdx.x;
    const int warp = tid >> 5;
    const int lane = tid & 31;
    const int wm   = warp >> 2;      // 0..3 -> rows wm*32
    const int wn   = warp & 3;       // 0..3 -> cols wn*32
    const int rowbase = blockIdx.x * BM;
    const int lrow4 = lane >> 2;     // 0..7
    const int lcol2 = (lane & 3) * 2;

    // Resident X tile [128][256] bf16 (padded rows)
#pragma unroll
    for (int t = 0; t < 16; ++t) {
        int idx = tid + t * NTHR;
        int r = idx >> 5, c8 = idx & 31;
        float4 v = *reinterpret_cast<const float4*>(g_Xb + (size_t)(rowbase + r) * D_DIM + c8 * 8);
        *reinterpret_cast<float4*>(Xs + r * XS + c8 * 8) = v;
    }
    if (tid < BM) rowminS[tid] = 0xFFFFFFFFu;

    auto load_blk = [&](int blk, int buf) {
        __nv_bfloat16* dst = buf ? Es1 : Es0;
        const __nv_bfloat16* src = g_Eb + (size_t)blk * BN * D_DIM;
#pragma unroll
        for (int t = 0; t < 8; ++t) {
            int idx = tid + t * NTHR;
            int r = idx >> 5, c8 = idx & 31;
            cp_async16(dst + r * XS + c8 * 8, src + r * D_DIM + c8 * 8);
        }
        if (tid < 32)
            cp_async16(&ensS[buf * BN + tid * 4], &g_enorm[blk * BN + tid * 4]);
    };

    load_blk(0, 0);
    cp_commit();

    // ldmatrix lane addressing: row = lane&15 within 16-row tile, +8 bf16 for
    // k-half when lane>=16.
    const uint32_t sXs = (uint32_t)__cvta_generic_to_shared(Xs);
    const int lrow16 = lane & 15;
    const int khalf  = (lane & 16) ? 16 : 0;   // bytes
    uint32_t aA[2];
#pragma unroll
    for (int mt = 0; mt < 2; ++mt)
        aA[mt] = sXs + (uint32_t)((wm * 32 + mt * 16 + lrow16) * XS * 2) + khalf;

    for (int blk = 0; blk < NBLK; ++blk) {
        const int buf = blk & 1;
        cp_wait0();
        __syncthreads();   // E buf(blk) ready; all warps done reading buf(blk-1)
        if (blk + 1 < NBLK) { load_blk(blk + 1, buf ^ 1); cp_commit(); }

        const __nv_bfloat16* Eb = buf ? Es1 : Es0;
        const uint32_t sEb = (uint32_t)__cvta_generic_to_shared(Eb);
        uint32_t aB[2];
#pragma unroll
        for (int n2 = 0; n2 < 2; ++n2)
            aB[n2] = sEb + (uint32_t)((wn * 32 + n2 * 16 + lrow16) * XS * 2) + khalf;

        float acc[2][4][4];
#pragma unroll
        for (int mt = 0; mt < 2; ++mt)
#pragma unroll
            for (int nt = 0; nt < 4; ++nt)
#pragma unroll
                for (int i = 0; i < 4; ++i) acc[mt][nt][i] = 0.f;

#pragma unroll
        for (int ks = 0; ks < 16; ++ks) {
            const uint32_t kb = ks * 32;   // 16 bf16 = 32 bytes
            uint32_t A[2][4];
            ldmat4(A[0][0], A[0][1], A[0][2], A[0][3], aA[0] + kb);
            ldmat4(A[1][0], A[1][1], A[1][2], A[1][3], aA[1] + kb);
            uint32_t B0[4], B1[4];
            ldmat4(B0[0], B0[1], B0[2], B0[3], aB[0] + kb);
            ldmat4(B1[0], B1[1], B1[2], B1[3], aB[1] + kb);
#pragma unroll
            for (int mt = 0; mt < 2; ++mt) {
                mma_bf16(acc[mt][0], A[mt], B0[0], B0[2]);
                mma_bf16(acc[mt][1], A[mt], B0[1], B0[3]);
                mma_bf16(acc[mt][2], A[mt], B1[0], B1[2]);
                mma_bf16(acc[mt][3], A[mt], B1[1], B1[3]);
            }
        }

        // dist = ||e||^2 - 2 x.e  (||x||^2 argmin-invariant)
        float e2[4][2];
#pragma unroll
        for (int nt = 0; nt < 4; ++nt) {
            int c = wn * 32 + nt * 8 + lcol2;
            e2[nt][0] = ensS[buf * BN + c];
            e2[nt][1] = ensS[buf * BN + c + 1];
        }
        float smin[4] = {FLT_MAX, FLT_MAX, FLT_MAX, FLT_MAX};
#pragma unroll
        for (int mt = 0; mt < 2; ++mt)
#pragma unroll
            for (int nt = 0; nt < 4; ++nt)
#pragma unroll
                for (int i = 0; i < 4; ++i) {
                    float d = fmaf(-2.0f, acc[mt][nt][i], e2[nt][i & 1]);
                    acc[mt][nt][i] = d;
                    int s = mt * 2 + (i >> 1);
                    smin[s] = fminf(smin[s], d);
                }
        // reduce the 4 lanes sharing each row
#pragma unroll
        for (int s = 0; s < 4; ++s) {
            smin[s] = fminf(smin[s], __shfl_xor_sync(0xffffffffu, smin[s], 1));
            smin[s] = fminf(smin[s], __shfl_xor_sync(0xffffffffu, smin[s], 2));
        }
        if ((lane & 3) == 0) {
#pragma unroll
            for (int s = 0; s < 4; ++s) {
                int lr = wm * 32 + (s >> 1) * 16 + lrow4 + 8 * (s & 1);
                atomicMin(&rowminS[lr], enc_f(smin[s]));
            }
        }
        // No sync: a stale (larger) rowmin only loosens the threshold, which
        // keeps the candidate set a superset (MARGIN > 2*bf16 error bound).
        float thr[4];
#pragma unroll
        for (int s = 0; s < 4; ++s) {
            int lr = wm * 32 + (s >> 1) * 16 + lrow4 + 8 * (s & 1);
            thr[s] = dec_f(rowminS[lr]) + MARGIN;
        }
#pragma unroll
        for (int mt = 0; mt < 2; ++mt)
#pragma unroll
            for (int nt = 0; nt < 4; ++nt)
#pragma unroll
                for (int i = 0; i < 4; ++i) {
                    int s = mt * 2 + (i >> 1);
                    if (acc[mt][nt][i] < thr[s]) {
                        int lr = wm * 32 + mt * 16 + lrow4 + 8 * (i >> 1);
                        int grow = rowbase + lr;
                        int gcol = blk * BN + wn * 32 + nt * 8 + lcol2 + (i & 1);
                        int pos = atomicAdd(&g_candcnt[grow], 1);
                        if (pos < CAND_CAP) g_cand[grow * CAND_CAP + pos] = gcol;
                    }
                }
    }
}

// ---------------------------------------------------------------------------
// Kernel D: exact fp32 rescue over candidates. One warp per row.
// ---------------------------------------------------------------------------
__global__ void vq_rescue_kernel(const float* __restrict__ X,
                                 const float* __restrict__ E) {
    int warp = threadIdx.x >> 5;
    int lane = threadIdx.x & 31;
    int row  = blockIdx.x * 8 + warp;

    const float4* x4 = reinterpret_cast<const float4*>(X + (size_t)row * D_DIM);
    float4 xa = x4[lane];
    float4 xb = x4[lane + 32];

    int cnt = g_candcnt[row];
    float best = FLT_MAX;
    int   bidx = 0x7fffffff;

    auto eval = [&](int idx) {
        const float4* e4 = reinterpret_cast<const float4*>(E + (size_t)idx * D_DIM);
        float4 ea = e4[lane];
        float4 eb = e4[lane + 32];
        float p = xa.x * ea.x + xa.y * ea.y + xa.z * ea.z + xa.w * ea.w
                + xb.x * eb.x + xb.y * eb.y + xb.z * eb.z + xb.w * eb.w;
#pragma unroll
        for (int off = 16; off >= 1; off >>= 1)
            p += __shfl_xor_sync(0xffffffffu, p, off);
        float dist = g_enorm[idx] - 2.0f * p;
        if (dist < best || (dist == best && idx < bidx)) { best = dist; bidx = idx; }
    };

    if (cnt > 0 && cnt <= CAND_CAP) {
        for (int c = 0; c < cnt; ++c) eval(g_cand[row * CAND_CAP + c]);
    } else {
        for (int k = 0; k < K_EMB; ++k) eval(k);   // overflow fallback (rare)
    }
    if (lane == 0) g_indices[row] = bidx;
}

// ---------------------------------------------------------------------------
// Kernel E: gather quantized rows + partial loss sums.
// ---------------------------------------------------------------------------
__global__ void vq_gather_kernel(const float* __restrict__ X,
                                 const float* __restrict__ E,
                                 float* __restrict__ out_q,
                                 float* __restrict__ out_idx_f,
                                 int*   __restrict__ out_idx_i) {
    __shared__ float wsum[8];
    int warp = threadIdx.x >> 5;
    int lane = threadIdx.x & 31;
    int row  = blockIdx.x * 8 + warp;

    int idx = g_indices[row];
    const float4* x4 = reinterpret_cast<const float4*>(X + (size_t)row * D_DIM);
    const float4* e4 = reinterpret_cast<const float4*>(E + (size_t)idx * D_DIM);

    float s = 0.f;
#pragma unroll
    for (int t = 0; t < 2; ++t) {
        int c = lane + 32 * t;
        float4 xv = x4[c];
        float4 ev = e4[c];
        if (out_q) reinterpret_cast<float4*>(out_q + (size_t)row * D_DIM)[c] = ev;
        float dx = ev.x - xv.x, dy = ev.y - xv.y, dz = ev.z - xv.z, dw = ev.w - xv.w;
        s += dx * dx + dy * dy + dz * dz + dw * dw;
    }
#pragma unroll
    for (int off = 16; off >= 1; off >>= 1)
        s += __shfl_xor_sync(0xffffffffu, s, off);
    if (lane == 0) {
        wsum[warp] = s;
        if (out_idx_f) out_idx_f[row] = (float)idx;
        if (out_idx_i) out_idx_i[row] = idx;
    }
    __syncthreads();
    if (threadIdx.x == 0) {
        float t = 0.f;
#pragma unroll
        for (int w = 0; w < 8; ++w) t += wsum[w];
        g_partial[blockIdx.x] = t;
    }
}

// ---------------------------------------------------------------------------
// Kernel F: loss = m + 0.25*m, m = sum/NQ.
// ---------------------------------------------------------------------------
__global__ void vq_loss_kernel(float* __restrict__ out_loss) {
    __shared__ float red[256];
    float s = 0.f;
#pragma unroll
    for (int t = 0; t < 8; ++t) s += g_partial[threadIdx.x + t * 256];
    red[threadIdx.x] = s;
    __syncthreads();
    for (int off = 128; off >= 1; off >>= 1) {
        if (threadIdx.x < off) red[threadIdx.x] += red[threadIdx.x + off];
        __syncthreads();
    }
    if (threadIdx.x == 0) {
        float m = red[0] / (float)NQ_ELEMS;
        *out_loss = m + 0.25f * m;
    }
}

// ---------------------------------------------------------------------------
extern "C" void kernel_launch(void* const* d_in, const int* in_sizes, int n_in,
                              void* d_out, int out_size) {
    const float* X = (const float*)d_in[0];
    const float* E = (const float*)d_in[1];
    float* out = (float*)d_out;

    float* out_q     = nullptr;
    float* out_loss  = nullptr;
    float* out_idx_f = nullptr;
    int*   out_idx_i = nullptr;

    if (out_size == NQ_ELEMS) {
        out_q = out;
    } else if (out_size == NQ_ELEMS + 1) {
        out_q = out; out_loss = out + NQ_ELEMS;
    } else if (out_size == NQ_ELEMS + 1 + N_ROWS) {
        out_q = out; out_loss = out + NQ_ELEMS; out_idx_f = out + NQ_ELEMS + 1;
    } else if (out_size == NQ_ELEMS + N_ROWS) {
        out_q = out; out_idx_f = out + NQ_ELEMS;
    } else if (out_size == N_ROWS) {
        out_idx_i = (int*)d_out;
    } else {
        out_q = out;
    }

    __nv_bfloat16 *dXb, *dEb;
    cudaGetSymbolAddress((void**)&dXb, g_Xb);
    cudaGetSymbolAddress((void**)&dEb, g_Eb);

    // A) bf16 copies
    vq_tobf16_kernel<<<NQ_ELEMS / 4 / 256, 256>>>(X, dXb, NQ_ELEMS / 4);
    vq_tobf16_kernel<<<K_EMB * D_DIM / 4 / 256, 256>>>(E, dEb, K_EMB * D_DIM / 4);

    // B) codebook norms + zero cand counters
    vq_enorm_kernel<<<K_EMB / 8, 256>>>(E);

    // C) coarse bf16 mma + candidate collection
    const int smem_bytes = (BM * XS + 2 * BN * XS) * 2 + 2 * BN * 4 + BM * 4;
    cudaFuncSetAttribute(vq_coarse_kernel,
                         cudaFuncAttributeMaxDynamicSharedMemorySize, smem_bytes);
    vq_coarse_kernel<<<N_ROWS / BM, NTHR, smem_bytes>>>();

    // D) exact fp32 rescue
    vq_rescue_kernel<<<N_ROWS / 8, 256>>>(X, E);

    // E) gather + partial loss sums
    vq_gather_kernel<<<N_ROWS / 8, 256>>>(X, E, out_q, out_idx_f, out_idx_i);

    // F) loss scalar
    if (out_loss) vq_loss_kernel<<<1, 256>>>(out_loss);
}

// round 5
// speedup vs baseline: 4.1548x; 1.0189x over previous
#include <cuda_runtime.h>
#include <cuda_bf16.h>
#include <float.h>
#include <stdint.h>

// ---------------------------------------------------------------------------
// Problem dims
// ---------------------------------------------------------------------------
#define N_ROWS 16384     // 32*512
#define K_EMB  8192
#define D_DIM  256
#define NQ_ELEMS (N_ROWS * D_DIM)   // 4194304

// Coarse-kernel tiling
#define BM 128           // rows per CTA
#define BN 128           // codes per col-block
#define NBLK (K_EMB / BN)    // 64
#define XS 264           // padded bf16 row stride: 528B -> 4-bank shift per row
#define MARGIN 3.0f
#define CAND_CAP 64
#define NTHR 512         // 16 warps: 4(m) x 4(n), warp tile 32x32

// ---------------------------------------------------------------------------
// Scratch (device globals; no allocations allowed)
// ---------------------------------------------------------------------------
__device__ float          g_enorm[K_EMB];
__device__ int            g_indices[N_ROWS];
__device__ float          g_partial[2048];
__device__ __nv_bfloat16  g_Xb[NQ_ELEMS];
__device__ __nv_bfloat16  g_Eb[K_EMB * D_DIM];
__device__ int            g_candcnt[N_ROWS];
__device__ int            g_cand[N_ROWS * CAND_CAP];

// ---------------------------------------------------------------------------
// Helpers
// ---------------------------------------------------------------------------
__device__ __forceinline__ unsigned enc_f(float f) {
    unsigned u = __float_as_uint(f);
    return (u & 0x80000000u) ? ~u : (u | 0x80000000u);
}
__device__ __forceinline__ float dec_f(unsigned k) {
    return (k & 0x80000000u) ? __uint_as_float(k & 0x7FFFFFFFu)
                             : __uint_as_float(~k);
}

__device__ __forceinline__ void cp_async16(void* smem_dst, const void* gsrc) {
    unsigned saddr = (unsigned)__cvta_generic_to_shared(smem_dst);
    asm volatile("cp.async.cg.shared.global [%0], [%1], 16;"
                 :: "r"(saddr), "l"(gsrc) : "memory");
}
__device__ __forceinline__ void cp_commit() {
    asm volatile("cp.async.commit_group;" ::: "memory");
}
__device__ __forceinline__ void cp_wait0() {
    asm volatile("cp.async.wait_group 0;" ::: "memory");
}

__device__ __forceinline__ void ldmat4(uint32_t* r, uint32_t addr) {
    asm volatile("ldmatrix.sync.aligned.m8n8.x4.shared.b16 {%0,%1,%2,%3}, [%4];"
                 : "=r"(r[0]), "=r"(r[1]), "=r"(r[2]), "=r"(r[3]) : "r"(addr));
}

__device__ __forceinline__ void mma_bf16(float* d, const uint32_t* a,
                                         uint32_t b0, uint32_t b1) {
    asm volatile(
        "mma.sync.aligned.m16n8k16.row.col.f32.bf16.bf16.f32 "
        "{%0,%1,%2,%3}, {%4,%5,%6,%7}, {%8,%9}, {%0,%1,%2,%3};"
        : "+f"(d[0]), "+f"(d[1]), "+f"(d[2]), "+f"(d[3])
        : "r"(a[0]), "r"(a[1]), "r"(a[2]), "r"(a[3]), "r"(b0), "r"(b1));
}

// ---------------------------------------------------------------------------
// Kernel A: fp32 -> bf16 (rn). n4 = n/4.
// ---------------------------------------------------------------------------
__global__ void vq_tobf16_kernel(const float* __restrict__ src,
                                 __nv_bfloat16* __restrict__ dst, int n4) {
    int i = blockIdx.x * blockDim.x + threadIdx.x;
    if (i >= n4) return;
    float4 v = reinterpret_cast<const float4*>(src)[i];
    __nv_bfloat162* d2 = reinterpret_cast<__nv_bfloat162*>(dst);
    d2[2 * i + 0] = __floats2bfloat162_rn(v.x, v.y);
    d2[2 * i + 1] = __floats2bfloat162_rn(v.z, v.w);
}

// ---------------------------------------------------------------------------
// Kernel B: ||e_k||^2 (fp32) + zero candidate counters.
// ---------------------------------------------------------------------------
__global__ void vq_enorm_kernel(const float* __restrict__ emb) {
    int gt = blockIdx.x * blockDim.x + threadIdx.x;
    if (gt < N_ROWS) g_candcnt[gt] = 0;
    int gw   = gt >> 5;
    int lane = threadIdx.x & 31;
    if (gw >= K_EMB) return;
    const float4* e4 = reinterpret_cast<const float4*>(emb + (size_t)gw * D_DIM);
    float s = 0.f;
#pragma unroll
    for (int i = 0; i < 2; ++i) {
        float4 v = e4[lane + 32 * i];
        s += v.x * v.x + v.y * v.y + v.z * v.z + v.w * v.w;
    }
#pragma unroll
    for (int off = 16; off >= 1; off >>= 1)
        s += __shfl_xor_sync(0xffffffffu, s, off);
    if (lane == 0) g_enorm[gw] = s;
}

// ---------------------------------------------------------------------------
// Kernel C: coarse bf16 GEMM (pipelined ldmatrix + mma.sync) + row-min +
// candidate collection.
// Grid = 128 CTAs, 512 threads (16 warps: 4m x 4n). Warp tile 32x32.
// ---------------------------------------------------------------------------
__global__ void __launch_bounds__(NTHR, 1)
vq_coarse_kernel() {
    extern __shared__ __align__(16) char smem[];
    __nv_bfloat16* Xs  = reinterpret_cast<__nv_bfloat16*>(smem);
    __nv_bfloat16* Es0 = Xs + BM * XS;
    __nv_bfloat16* Es1 = Es0 + BN * XS;
    float*    ensS    = reinterpret_cast<float*>(Es1 + BN * XS);  // [2][128]
    unsigned* rowminS = reinterpret_cast<unsigned*>(ensS + 2 * BN);

    const int tid  = threadIdx.x;
    const int warp = tid >> 5;
    const int lane = tid & 31;
    const int wm   = warp >> 2;      // 0..3 -> rows wm*32
    const int wn   = warp & 3;       // 0..3 -> cols wn*32
    const int rowbase = blockIdx.x * BM;
    const int lrow4 = lane >> 2;     // 0..7
    const int lcol2 = (lane & 3) * 2;

    // Resident X tile [128][256] bf16 (padded rows)
#pragma unroll
    for (int t = 0; t < 16; ++t) {
        int idx = tid + t * NTHR;
        int r = idx >> 5, c8 = idx & 31;
        float4 v = *reinterpret_cast<const float4*>(g_Xb + (size_t)(rowbase + r) * D_DIM + c8 * 8);
        *reinterpret_cast<float4*>(Xs + r * XS + c8 * 8) = v;
    }
    if (tid < BM) rowminS[tid] = 0xFFFFFFFFu;

    auto load_blk = [&](int blk, int buf) {
        __nv_bfloat16* dst = buf ? Es1 : Es0;
        const __nv_bfloat16* src = g_Eb + (size_t)blk * BN * D_DIM;
#pragma unroll
        for (int t = 0; t < 8; ++t) {
            int idx = tid + t * NTHR;
            int r = idx >> 5, c8 = idx & 31;
            cp_async16(dst + r * XS + c8 * 8, src + r * D_DIM + c8 * 8);
        }
        if (tid < 32)
            cp_async16(&ensS[buf * BN + tid * 4], &g_enorm[blk * BN + tid * 4]);
    };

    load_blk(0, 0);
    cp_commit();

    // ldmatrix lane addressing: row = lane&15 within 16-row tile, +8 bf16 for
    // k-half when lane>=16.
    const uint32_t sXs = (uint32_t)__cvta_generic_to_shared(Xs);
    const int lrow16 = lane & 15;
    const int khalf  = (lane & 16) ? 16 : 0;   // bytes
    uint32_t aA[2];
#pragma unroll
    for (int mt = 0; mt < 2; ++mt)
        aA[mt] = sXs + (uint32_t)((wm * 32 + mt * 16 + lrow16) * XS * 2) + khalf;

    for (int blk = 0; blk < NBLK; ++blk) {
        const int buf = blk & 1;
        cp_wait0();
        __syncthreads();   // E buf(blk) ready; all warps done reading buf(blk-1)
        if (blk + 1 < NBLK) { load_blk(blk + 1, buf ^ 1); cp_commit(); }

        const __nv_bfloat16* Eb = buf ? Es1 : Es0;
        const uint32_t sEb = (uint32_t)__cvta_generic_to_shared(Eb);
        uint32_t aB[2];
#pragma unroll
        for (int n2 = 0; n2 < 2; ++n2)
            aB[n2] = sEb + (uint32_t)((wn * 32 + n2 * 16 + lrow16) * XS * 2) + khalf;

        float acc[2][4][4];
#pragma unroll
        for (int mt = 0; mt < 2; ++mt)
#pragma unroll
            for (int nt = 0; nt < 4; ++nt)
#pragma unroll
                for (int i = 0; i < 4; ++i) acc[mt][nt][i] = 0.f;

        // Software-pipelined fragment double buffer: LDSM(ks+1) issued before
        // HMMA(ks) so the ~30cyc LDS latency hides behind 8 HMMAs + arbiter.
        uint32_t FA[2][2][4];   // [bank][mt][frag]
        uint32_t FB[2][2][4];   // [bank][n2][frag]
        ldmat4(FA[0][0], aA[0]);
        ldmat4(FA[0][1], aA[1]);
        ldmat4(FB[0][0], aB[0]);
        ldmat4(FB[0][1], aB[1]);

#pragma unroll
        for (int ks = 0; ks < 16; ++ks) {
            const int cur = ks & 1, nxt = cur ^ 1;
            if (ks < 15) {
                const uint32_t kb = (uint32_t)(ks + 1) * 32;   // 16 bf16 = 32B
                ldmat4(FA[nxt][0], aA[0] + kb);
                ldmat4(FA[nxt][1], aA[1] + kb);
                ldmat4(FB[nxt][0], aB[0] + kb);
                ldmat4(FB[nxt][1], aB[1] + kb);
            }
#pragma unroll
            for (int mt = 0; mt < 2; ++mt) {
                mma_bf16(acc[mt][0], FA[cur][mt], FB[cur][0][0], FB[cur][0][2]);
                mma_bf16(acc[mt][1], FA[cur][mt], FB[cur][0][1], FB[cur][0][3]);
                mma_bf16(acc[mt][2], FA[cur][mt], FB[cur][1][0], FB[cur][1][2]);
                mma_bf16(acc[mt][3], FA[cur][mt], FB[cur][1][1], FB[cur][1][3]);
            }
        }

        // dist = ||e||^2 - 2 x.e  (||x||^2 argmin-invariant)
        float e2[4][2];
#pragma unroll
        for (int nt = 0; nt < 4; ++nt) {
            int c = wn * 32 + nt * 8 + lcol2;
            e2[nt][0] = ensS[buf * BN + c];
            e2[nt][1] = ensS[buf * BN + c + 1];
        }
        float smin[4] = {FLT_MAX, FLT_MAX, FLT_MAX, FLT_MAX};
#pragma unroll
        for (int mt = 0; mt < 2; ++mt)
#pragma unroll
            for (int nt = 0; nt < 4; ++nt)
#pragma unroll
                for (int i = 0; i < 4; ++i) {
                    float d = fmaf(-2.0f, acc[mt][nt][i], e2[nt][i & 1]);
                    acc[mt][nt][i] = d;
                    int s = mt * 2 + (i >> 1);
                    smin[s] = fminf(smin[s], d);
                }
        float tmin[4];   // per-thread (pre-shuffle) minima, for the early-out
#pragma unroll
        for (int s = 0; s < 4; ++s) tmin[s] = smin[s];
        // reduce the 4 lanes sharing each row
#pragma unroll
        for (int s = 0; s < 4; ++s) {
            smin[s] = fminf(smin[s], __shfl_xor_sync(0xffffffffu, smin[s], 1));
            smin[s] = fminf(smin[s], __shfl_xor_sync(0xffffffffu, smin[s], 2));
        }
        if ((lane & 3) == 0) {
#pragma unroll
            for (int s = 0; s < 4; ++s) {
                int lr = wm * 32 + (s >> 1) * 16 + lrow4 + 8 * (s & 1);
                atomicMin(&rowminS[lr], enc_f(smin[s]));
            }
        }
        // No sync: a stale (larger) rowmin only loosens the threshold, which
        // keeps the candidate set a superset (MARGIN > 2*bf16 error bound).
        float thr[4];
#pragma unroll
        for (int s = 0; s < 4; ++s) {
            int lr = wm * 32 + (s >> 1) * 16 + lrow4 + 8 * (s & 1);
            thr[s] = dec_f(rowminS[lr]) + MARGIN;
        }
        // Early-out: most blocks contribute no candidates for this thread.
        bool any = (tmin[0] < thr[0]) | (tmin[1] < thr[1]) |
                   (tmin[2] < thr[2]) | (tmin[3] < thr[3]);
        if (any) {
#pragma unroll
            for (int mt = 0; mt < 2; ++mt)
#pragma unroll
                for (int nt = 0; nt < 4; ++nt)
#pragma unroll
                    for (int i = 0; i < 4; ++i) {
                        int s = mt * 2 + (i >> 1);
                        if (acc[mt][nt][i] < thr[s]) {
                            int lr = wm * 32 + mt * 16 + lrow4 + 8 * (i >> 1);
                            int grow = rowbase + lr;
                            int gcol = blk * BN + wn * 32 + nt * 8 + lcol2 + (i & 1);
                            int pos = atomicAdd(&g_candcnt[grow], 1);
                            if (pos < CAND_CAP) g_cand[grow * CAND_CAP + pos] = gcol;
                        }
                    }
        }
    }
}

// ---------------------------------------------------------------------------
// Kernel D: exact fp32 rescue over candidates. One warp per row.
// ---------------------------------------------------------------------------
__global__ void vq_rescue_kernel(const float* __restrict__ X,
                                 const float* __restrict__ E) {
    int warp = threadIdx.x >> 5;
    int lane = threadIdx.x & 31;
    int row  = blockIdx.x * 8 + warp;

    const float4* x4 = reinterpret_cast<const float4*>(X + (size_t)row * D_DIM);
    float4 xa = x4[lane];
    float4 xb = x4[lane + 32];

    int cnt = g_candcnt[row];
    float best = FLT_MAX;
    int   bidx = 0x7fffffff;

    auto eval = [&](int idx) {
        const float4* e4 = reinterpret_cast<const float4*>(E + (size_t)idx * D_DIM);
        float4 ea = e4[lane];
        float4 eb = e4[lane + 32];
        float p = xa.x * ea.x + xa.y * ea.y + xa.z * ea.z + xa.w * ea.w
                + xb.x * eb.x + xb.y * eb.y + xb.z * eb.z + xb.w * eb.w;
#pragma unroll
        for (int off = 16; off >= 1; off >>= 1)
            p += __shfl_xor_sync(0xffffffffu, p, off);
        float dist = g_enorm[idx] - 2.0f * p;
        if (dist < best || (dist == best && idx < bidx)) { best = dist; bidx = idx; }
    };

    if (cnt > 0 && cnt <= CAND_CAP) {
        for (int c = 0; c < cnt; ++c) eval(g_cand[row * CAND_CAP + c]);
    } else {
        for (int k = 0; k < K_EMB; ++k) eval(k);   // overflow fallback (rare)
    }
    if (lane == 0) g_indices[row] = bidx;
}

// ---------------------------------------------------------------------------
// Kernel E: gather quantized rows + partial loss sums.
// ---------------------------------------------------------------------------
__global__ void vq_gather_kernel(const float* __restrict__ X,
                                 const float* __restrict__ E,
                                 float* __restrict__ out_q,
                                 float* __restrict__ out_idx_f,
                                 int*   __restrict__ out_idx_i) {
    __shared__ float wsum[8];
    int warp = threadIdx.x >> 5;
    int lane = threadIdx.x & 31;
    int row  = blockIdx.x * 8 + warp;

    int idx = g_indices[row];
    const float4* x4 = reinterpret_cast<const float4*>(X + (size_t)row * D_DIM);
    const float4* e4 = reinterpret_cast<const float4*>(E + (size_t)idx * D_DIM);

    float s = 0.f;
#pragma unroll
    for (int t = 0; t < 2; ++t) {
        int c = lane + 32 * t;
        float4 xv = x4[c];
        float4 ev = e4[c];
        if (out_q) reinterpret_cast<float4*>(out_q + (size_t)row * D_DIM)[c] = ev;
        float dx = ev.x - xv.x, dy = ev.y - xv.y, dz = ev.z - xv.z, dw = ev.w - xv.w;
        s += dx * dx + dy * dy + dz * dz + dw * dw;
    }
#pragma unroll
    for (int off = 16; off >= 1; off >>= 1)
        s += __shfl_xor_sync(0xffffffffu, s, off);
    if (lane == 0) {
        wsum[warp] = s;
        if (out_idx_f) out_idx_f[row] = (float)idx;
        if (out_idx_i) out_idx_i[row] = idx;
    }
    __syncthreads();
    if (threadIdx.x == 0) {
        float t = 0.f;
#pragma unroll
        for (int w = 0; w < 8; ++w) t += wsum[w];
        g_partial[blockIdx.x] = t;
    }
}

// ---------------------------------------------------------------------------
// Kernel F: loss = m + 0.25*m, m = sum/NQ.
// ---------------------------------------------------------------------------
__global__ void vq_loss_kernel(float* __restrict__ out_loss) {
    __shared__ float red[256];
    float s = 0.f;
#pragma unroll
    for (int t = 0; t < 8; ++t) s += g_partial[threadIdx.x + t * 256];
    red[threadIdx.x] = s;
    __syncthreads();
    for (int off = 128; off >= 1; off >>= 1) {
        if (threadIdx.x < off) red[threadIdx.x] += red[threadIdx.x + off];
        __syncthreads();
    }
    if (threadIdx.x == 0) {
        float m = red[0] / (float)NQ_ELEMS;
        *out_loss = m + 0.25f * m;
    }
}

// ---------------------------------------------------------------------------
extern "C" void kernel_launch(void* const* d_in, const int* in_sizes, int n_in,
                              void* d_out, int out_size) {
    const float* X = (const float*)d_in[0];
    const float* E = (const float*)d_in[1];
    float* out = (float*)d_out;

    float* out_q     = nullptr;
    float* out_loss  = nullptr;
    float* out_idx_f = nullptr;
    int*   out_idx_i = nullptr;

    if (out_size == NQ_ELEMS) {
        out_q = out;
    } else if (out_size == NQ_ELEMS + 1) {
        out_q = out; out_loss = out + NQ_ELEMS;
    } else if (out_size == NQ_ELEMS + 1 + N_ROWS) {
        out_q = out; out_loss = out + NQ_ELEMS; out_idx_f = out + NQ_ELEMS + 1;
    } else if (out_size == NQ_ELEMS + N_ROWS) {
        out_q = out; out_idx_f = out + NQ_ELEMS;
    } else if (out_size == N_ROWS) {
        out_idx_i = (int*)d_out;
    } else {
        out_q = out;
    }

    __nv_bfloat16 *dXb, *dEb;
    cudaGetSymbolAddress((void**)&dXb, g_Xb);
    cudaGetSymbolAddress((void**)&dEb, g_Eb);

    // A) bf16 copies
    vq_tobf16_kernel<<<NQ_ELEMS / 4 / 256, 256>>>(X, dXb, NQ_ELEMS / 4);
    vq_tobf16_kernel<<<K_EMB * D_DIM / 4 / 256, 256>>>(E, dEb, K_EMB * D_DIM / 4);

    // B) codebook norms + zero cand counters
    vq_enorm_kernel<<<K_EMB / 8, 256>>>(E);

    // C) coarse bf16 mma + candidate collection
    const int smem_bytes = (BM * XS + 2 * BN * XS) * 2 + 2 * BN * 4 + BM * 4;
    cudaFuncSetAttribute(vq_coarse_kernel,
                         cudaFuncAttributeMaxDynamicSharedMemorySize, smem_bytes);
    vq_coarse_kernel<<<N_ROWS / BM, NTHR, smem_bytes>>>();

    // D) exact fp32 rescue
    vq_rescue_kernel<<<N_ROWS / 8, 256>>>(X, E);

    // E) gather + partial loss sums
    vq_gather_kernel<<<N_ROWS / 8, 256>>>(X, E, out_q, out_idx_f, out_idx_i);

    // F) loss scalar
    if (out_loss) vq_loss_kernel<<<1, 256>>>(out_loss);
}